// round 5
// baseline (speedup 1.0000x reference)
#include <cuda_runtime.h>

#define NB      8
#define NHEADS  12
#define HH      24
#define SEQ     576
#define DIM     64
#define NPOS    24
#define BATCH   96
#define KPAD    28          // row stride: 16B-aligned AND conflict-free for strided 8x8 micro rows

// Scratch: pe_x_flat / pe_y_flat  [BATCH][SEQ][NPOS]
__device__ __align__(16) float g_Vx[BATCH * SEQ * NPOS];
__device__ __align__(16) float g_Vy[BATCH * SEQ * NPOS];

__device__ __forceinline__ float sigmoidf_(float x) {
    return 1.0f / (1.0f + __expf(-x));
}

__device__ __forceinline__ unsigned long long fma2(unsigned long long a,
                                                   unsigned long long b,
                                                   unsigned long long c) {
    unsigned long long d;
    asm("fma.rn.f32x2 %0, %1, %2, %3;" : "=l"(d) : "l"(a), "l"(b), "l"(c));
    return d;
}

__device__ __forceinline__ unsigned long long pack2(float lo, float hi) {
    unsigned long long r;
    asm("mov.b64 %0, {%1, %2};" : "=l"(r) : "f"(lo), "f"(hi));
    return r;
}

__device__ __forceinline__ float fsqrt_approx(float x) {
    float r;
    asm("sqrt.approx.f32 %0, %1;" : "=f"(r) : "f"(x));
    return r;
}

// ---------------------------------------------------------------------------
// Kernel 1: fused CoPE, both paths in one block (512 threads, path = t>>8).
// blockIdx.x = id in [0, 2304); id = n*12 + m.
// ---------------------------------------------------------------------------
__global__ void __launch_bounds__(512) cope_kernel(
    const float* __restrict__ query,      // [8,12,576,64]
    const float* __restrict__ attn,       // [8,12,576,576]
    const float* __restrict__ pex,        // [64,24]
    const float* __restrict__ pey)        // [64,24]
{
    __shared__ __align__(16) float q_s[2][HH * 68];       // pad 68 (16B-aligned rows)
    __shared__ __align__(16) float pe_s[2][DIM * NPOS];
    __shared__ __align__(8)  float li[2][HH * 26];

    int t    = threadIdx.x;
    int path = t >> 8;
    int tp   = t & 255;

    int id   = blockIdx.x;
    int n    = id / 12;
    int m    = id % 12;
    // attn-side decomposition (faithful to reshape-without-permute)
    int b_a  = id / 288;
    int hd_a = (id / 24) % 12;
    int r_a  = id % 24;
    // query-side decomposition
    int b_q  = n / 24;
    int s_q  = n % 24;

    // pe load (float4)
    {
        const float4* pe4 = (const float4*)(path ? pey : pex);
        float4* d4 = (float4*)pe_s[path];
        for (int idx = tp; idx < DIM * NPOS / 4; idx += 256)
            d4[idx] = pe4[idx];
    }

    // q load (float4)
    if (!path) {
        const float4* qb = (const float4*)(query + (((size_t)(b_q * 12 + m)) * SEQ + s_q * 24) * DIM);
        for (int idx = tp; idx < HH * DIM / 4; idx += 256) {
            int rr = idx >> 4, c4 = (idx & 15) * 4;
            *(float4*)&q_s[0][rr * 68 + c4] = qb[idx];
        }
    } else {
        const float* qb = query + (((size_t)(b_q * 12 + m)) * SEQ + s_q) * DIM;
        for (int idx = tp; idx < HH * DIM / 4; idx += 256) {
            int rr = idx >> 4, c4 = (idx & 15) * 4;
            *(float4*)&q_s[1][rr * 68 + c4] = *(const float4*)(qb + (size_t)rr * (24 * DIM) + c4);
        }
    }
    __syncthreads();

    // GEMM: per path 288 tasks = 24 j x 12 p-pairs; float4 q, one fma2 per d.
    for (int o = tp; o < HH * 12; o += 256) {
        int j  = o / 12;
        int pp = o - j * 12;
        const float4* qr4 = (const float4*)&q_s[path][j * 68];
        const float*  pr  = pe_s[path] + 2 * pp;
        unsigned long long acc = 0ull;
        #pragma unroll
        for (int dq = 0; dq < 16; dq++) {
            float4 q4 = qr4[dq];
            float2 v0 = *(const float2*)(pr + (4 * dq + 0) * NPOS);
            float2 v1 = *(const float2*)(pr + (4 * dq + 1) * NPOS);
            float2 v2 = *(const float2*)(pr + (4 * dq + 2) * NPOS);
            float2 v3 = *(const float2*)(pr + (4 * dq + 3) * NPOS);
            acc = fma2(pack2(q4.x, q4.x), pack2(v0.x, v0.y), acc);
            acc = fma2(pack2(q4.y, q4.y), pack2(v1.x, v1.y), acc);
            acc = fma2(pack2(q4.z, q4.z), pack2(v2.x, v2.y), acc);
            acc = fma2(pack2(q4.w, q4.w), pack2(v3.x, v3.y), acc);
        }
        *(float2*)(&li[path][j * 26 + 2 * pp]) = *(float2*)&acc;
    }
    __syncthreads();

    // Scan: per path 8 warps cover 24 rows in 3 passes.
    int w    = (t >> 5) & 7;
    int lane = t & 31;
    int bh   = b_q * 12 + m;
    for (int j = w; j < HH; j += 8) {
        const float* arow;
        int astride;
        float* dst;
        if (!path) {
            arow = attn + (((size_t)(b_a * 12 + hd_a)) * SEQ + (size_t)(r_a * 24 + j)) * SEQ
                        + (size_t)(r_a * 24);
            astride = 1;
            dst = g_Vx + ((size_t)bh * SEQ + (size_t)(s_q * 24 + j)) * NPOS;
        } else {
            arow = attn + (((size_t)(b_a * 12 + hd_a)) * SEQ + (size_t)(j * 24 + r_a)) * SEQ
                        + (size_t)r_a;
            astride = 24;
            dst = g_Vy + ((size_t)bh * SEQ + (size_t)(j * 24 + s_q)) * NPOS;
        }
        float v = 0.0f;
        if (lane < NPOS)
            v = sigmoidf_(arow[lane * astride]);
        #pragma unroll
        for (int d = 1; d < 32; d <<= 1) {
            float tv = __shfl_down_sync(0xffffffffu, v, d);
            if (lane + d < NPOS) v += tv;
        }
        if (lane < NPOS) {
            float pp = fminf(v, (float)(NPOS - 1));
            float pf = floorf(pp);
            int   ifl = (int)pf;
            int   ic  = (int)ceilf(pp);
            float wq  = pp - pf;
            float val = li[path][j * 26 + ic] * wq + li[path][j * 26 + ifl] * (1.0f - wq);
            dst[lane] = val;
        }
    }
}

// ---------------------------------------------------------------------------
// Kernel 2: fused double-cdist + mix. 128 threads = two 64-thread s-groups;
// each group computes one path's 64x64 Gram with an 8x8 micro-tile
// (strided rows ty+8i / tx+8j; KPAD=28 -> conflict-free LDS.64).
// Groups combine through padded smem tile xch, which then stages coalesced
// float4 primary + mirror writes.
// ---------------------------------------------------------------------------
__global__ void __launch_bounds__(128, 2) dist_kernel(
    const float* __restrict__ wxp,
    float* __restrict__ out)
{
    __shared__ __align__(16) float sA[2][64 * KPAD];
    __shared__ __align__(16) float sB[2][64 * KPAD];
    __shared__ float nA[2][64];
    __shared__ float nB[2][64];
    __shared__ float xch[64 * 65];

    int bz = blockIdx.y;
    int u = blockIdx.x;
    int ti = 0;
    #pragma unroll 1
    while (u >= (9 - ti)) { u -= (9 - ti); ti++; }
    int tj = ti + u;
    int p0 = ti * 64;
    int q0 = tj * 64;

    int t  = threadIdx.x;     // 0..127
    int sg = t >> 6;          // s-path group
    int lt = t & 63;
    int tx = lt & 7;
    int ty = lt >> 3;

    // Load 64x24 row blocks for both paths (float4 -> STS.128, rows 16B-aligned)
    #pragma unroll
    for (int s = 0; s < 2; s++) {
        const float* V = s ? g_Vy : g_Vx;
        const float4* ga = (const float4*)(V + ((size_t)bz * SEQ + p0) * NPOS);
        const float4* gb = (const float4*)(V + ((size_t)bz * SEQ + q0) * NPOS);
        for (int idx = t; idx < 64 * NPOS / 4; idx += 128) {   // 384 float4
            int r = idx / 6, c = (idx - r * 6) * 4;
            *(float4*)&sA[s][r * KPAD + c] = ga[idx];
            *(float4*)&sB[s][r * KPAD + c] = gb[idx];
        }
    }
    __syncthreads();

    // Row norms: 256 tasks on 128 threads
    for (int o = t; o < 256; o += 128) {
        int s  = (o >> 7) & 1;
        int ab = (o >> 6) & 1;
        int r  = o & 63;
        const float* src = ab ? &sB[s][r * KPAD] : &sA[s][r * KPAD];
        float acc = 0.0f;
        #pragma unroll
        for (int k = 0; k < NPOS; k++)
            acc = fmaf(src[k], src[k], acc);
        if (ab) nB[s][r] = acc; else nA[s][r] = acc;
    }
    __syncthreads();

    float wxv = *wxp;

    // Gram for this group's path: 8x8 micro-tile, fp32x2 accumulators.
    const float* As = sA[sg];
    const float* Bs = sB[sg];
    unsigned long long acc[64];
    #pragma unroll
    for (int u2 = 0; u2 < 64; u2++) acc[u2] = 0ull;

    #pragma unroll
    for (int kk = 0; kk < NPOS / 2; kk++) {
        unsigned long long a2[8], b2[8];
        #pragma unroll
        for (int i = 0; i < 8; i++)
            a2[i] = *(const unsigned long long*)(As + (ty + 8 * i) * KPAD + 2 * kk);
        #pragma unroll
        for (int j = 0; j < 8; j++)
            b2[j] = *(const unsigned long long*)(Bs + (tx + 8 * j) * KPAD + 2 * kk);
        #pragma unroll
        for (int i = 0; i < 8; i++)
            #pragma unroll
            for (int j = 0; j < 8; j++)
                acc[i * 8 + j] = fma2(a2[i], b2[j], acc[i * 8 + j]);
    }

    // s=1 group deposits scaled distances into xch
    if (sg == 1) {
        float scale = 1.0f - wxv;
        #pragma unroll
        for (int i = 0; i < 8; i++) {
            float na = nA[1][ty + 8 * i];
            #pragma unroll
            for (int j = 0; j < 8; j++) {
                float2 g = *(float2*)&acc[i * 8 + j];
                float d2 = fmaf(-2.0f, g.x + g.y, na + nB[1][tx + 8 * j]);
                d2 = fmaxf(d2, 0.0f);
                xch[(ty + 8 * i) * 65 + (tx + 8 * j)] = scale * fsqrt_approx(d2);
            }
        }
    }
    __syncthreads();

    // s=0 group combines, zeroes diagonal, stores final back to xch
    if (sg == 0) {
        float scale = wxv;
        #pragma unroll
        for (int i = 0; i < 8; i++) {
            float na = nA[0][ty + 8 * i];
            int p = p0 + ty + 8 * i;
            #pragma unroll
            for (int j = 0; j < 8; j++) {
                float2 g = *(float2*)&acc[i * 8 + j];
                float d2 = fmaf(-2.0f, g.x + g.y, na + nB[0][tx + 8 * j]);
                d2 = fmaxf(d2, 0.0f);
                int idx = (ty + 8 * i) * 65 + (tx + 8 * j);
                float f = fmaf(scale, fsqrt_approx(d2), xch[idx]);
                if (p == q0 + tx + 8 * j) f = 0.0f;
                xch[idx] = f;
            }
        }
    }
    __syncthreads();

    // Primary tile: coalesced float4 writes by all 128 threads
    for (int idx = t; idx < 1024; idx += 128) {
        int r = idx >> 4, c = (idx & 15) * 4;
        const float* xr = &xch[r * 65 + c];
        float4 v = make_float4(xr[0], xr[1], xr[2], xr[3]);
        *(float4*)(out + ((size_t)bz * SEQ + (p0 + r)) * SEQ + q0 + c) = v;
    }

    // Mirror tile for off-diagonal pairs (transposed reads, coalesced writes)
    if (ti != tj) {
        for (int idx = t; idx < 1024; idx += 128) {
            int r = idx >> 4, c = (idx & 15) * 4;
            float4 v = make_float4(xch[(c + 0) * 65 + r],
                                   xch[(c + 1) * 65 + r],
                                   xch[(c + 2) * 65 + r],
                                   xch[(c + 3) * 65 + r]);
            *(float4*)(out + ((size_t)bz * SEQ + (q0 + r)) * SEQ + p0 + c) = v;
        }
    }
}

// ---------------------------------------------------------------------------
extern "C" void kernel_launch(void* const* d_in, const int* in_sizes, int n_in,
                              void* d_out, int out_size) {
    const float* query = (const float*)d_in[0];
    const float* attn  = (const float*)d_in[1];
    const float* pex   = (const float*)d_in[2];
    const float* pey   = (const float*)d_in[3];
    const float* wx    = (const float*)d_in[4];
    float* out = (float*)d_out;

    cope_kernel<<<2304, 512>>>(query, attn, pex, pey);

    dim3 dgrid(45, BATCH);
    dist_kernel<<<dgrid, 128>>>(wx, out);
}

// round 6
// speedup vs baseline: 1.3078x; 1.3078x over previous
#include <cuda_runtime.h>

#define NB      8
#define NHEADS  12
#define HH      24
#define SEQ     576
#define DIM     64
#define NPOS    24
#define BATCH   96
#define KPAD    28          // B row stride (words): tx*28 mod 32 distinct for tx 0..7
#define ATPAD   66          // AT row stride (words): rows 8B-aligned (66*4=264)

// Scratch: pe_x_flat / pe_y_flat  [BATCH][SEQ][NPOS]
__device__ __align__(16) float g_Vx[BATCH * SEQ * NPOS];
__device__ __align__(16) float g_Vy[BATCH * SEQ * NPOS];

__device__ __forceinline__ float sigmoidf_(float x) {
    return 1.0f / (1.0f + __expf(-x));
}

__device__ __forceinline__ unsigned long long fma2(unsigned long long a,
                                                   unsigned long long b,
                                                   unsigned long long c) {
    unsigned long long d;
    asm("fma.rn.f32x2 %0, %1, %2, %3;" : "=l"(d) : "l"(a), "l"(b), "l"(c));
    return d;
}

__device__ __forceinline__ unsigned long long pack2(float lo, float hi) {
    unsigned long long r;
    asm("mov.b64 %0, {%1, %2};" : "=l"(r) : "f"(lo), "f"(hi));
    return r;
}

__device__ __forceinline__ float fsqrt_approx(float x) {
    float r;
    asm("sqrt.approx.f32 %0, %1;" : "=f"(r) : "f"(x));
    return r;
}

// ---------------------------------------------------------------------------
// Kernel 1: fused CoPE, both paths in one block (512 threads, path = t>>8).
// (unchanged from R5 — best cope so far)
// ---------------------------------------------------------------------------
__global__ void __launch_bounds__(512) cope_kernel(
    const float* __restrict__ query,      // [8,12,576,64]
    const float* __restrict__ attn,       // [8,12,576,576]
    const float* __restrict__ pex,        // [64,24]
    const float* __restrict__ pey)        // [64,24]
{
    __shared__ __align__(16) float q_s[2][HH * 68];
    __shared__ __align__(16) float pe_s[2][DIM * NPOS];
    __shared__ __align__(8)  float li[2][HH * 26];

    int t    = threadIdx.x;
    int path = t >> 8;
    int tp   = t & 255;

    int id   = blockIdx.x;
    int n    = id / 12;
    int m    = id % 12;
    int b_a  = id / 288;
    int hd_a = (id / 24) % 12;
    int r_a  = id % 24;
    int b_q  = n / 24;
    int s_q  = n % 24;

    {
        const float4* pe4 = (const float4*)(path ? pey : pex);
        float4* d4 = (float4*)pe_s[path];
        for (int idx = tp; idx < DIM * NPOS / 4; idx += 256)
            d4[idx] = pe4[idx];
    }

    if (!path) {
        const float4* qb = (const float4*)(query + (((size_t)(b_q * 12 + m)) * SEQ + s_q * 24) * DIM);
        for (int idx = tp; idx < HH * DIM / 4; idx += 256) {
            int rr = idx >> 4, c4 = (idx & 15) * 4;
            *(float4*)&q_s[0][rr * 68 + c4] = qb[idx];
        }
    } else {
        const float* qb = query + (((size_t)(b_q * 12 + m)) * SEQ + s_q) * DIM;
        for (int idx = tp; idx < HH * DIM / 4; idx += 256) {
            int rr = idx >> 4, c4 = (idx & 15) * 4;
            *(float4*)&q_s[1][rr * 68 + c4] = *(const float4*)(qb + (size_t)rr * (24 * DIM) + c4);
        }
    }
    __syncthreads();

    for (int o = tp; o < HH * 12; o += 256) {
        int j  = o / 12;
        int pp = o - j * 12;
        const float4* qr4 = (const float4*)&q_s[path][j * 68];
        const float*  pr  = pe_s[path] + 2 * pp;
        unsigned long long acc = 0ull;
        #pragma unroll
        for (int dq = 0; dq < 16; dq++) {
            float4 q4 = qr4[dq];
            float2 v0 = *(const float2*)(pr + (4 * dq + 0) * NPOS);
            float2 v1 = *(const float2*)(pr + (4 * dq + 1) * NPOS);
            float2 v2 = *(const float2*)(pr + (4 * dq + 2) * NPOS);
            float2 v3 = *(const float2*)(pr + (4 * dq + 3) * NPOS);
            acc = fma2(pack2(q4.x, q4.x), pack2(v0.x, v0.y), acc);
            acc = fma2(pack2(q4.y, q4.y), pack2(v1.x, v1.y), acc);
            acc = fma2(pack2(q4.z, q4.z), pack2(v2.x, v2.y), acc);
            acc = fma2(pack2(q4.w, q4.w), pack2(v3.x, v3.y), acc);
        }
        *(float2*)(&li[path][j * 26 + 2 * pp]) = *(float2*)&acc;
    }
    __syncthreads();

    int w    = (t >> 5) & 7;
    int lane = t & 31;
    int bh   = b_q * 12 + m;
    for (int j = w; j < HH; j += 8) {
        const float* arow;
        int astride;
        float* dst;
        if (!path) {
            arow = attn + (((size_t)(b_a * 12 + hd_a)) * SEQ + (size_t)(r_a * 24 + j)) * SEQ
                        + (size_t)(r_a * 24);
            astride = 1;
            dst = g_Vx + ((size_t)bh * SEQ + (size_t)(s_q * 24 + j)) * NPOS;
        } else {
            arow = attn + (((size_t)(b_a * 12 + hd_a)) * SEQ + (size_t)(j * 24 + r_a)) * SEQ
                        + (size_t)r_a;
            astride = 24;
            dst = g_Vy + ((size_t)bh * SEQ + (size_t)(j * 24 + s_q)) * NPOS;
        }
        float v = 0.0f;
        if (lane < NPOS)
            v = sigmoidf_(arow[lane * astride]);
        #pragma unroll
        for (int d = 1; d < 32; d <<= 1) {
            float tv = __shfl_down_sync(0xffffffffu, v, d);
            if (lane + d < NPOS) v += tv;
        }
        if (lane < NPOS) {
            float pp = fminf(v, (float)(NPOS - 1));
            float pf = floorf(pp);
            int   ifl = (int)pf;
            int   ic  = (int)ceilf(pp);
            float wq  = pp - pf;
            float val = li[path][j * 26 + ic] * wq + li[path][j * 26 + ifl] * (1.0f - wq);
            dst[lane] = val;
        }
    }
}

// ---------------------------------------------------------------------------
// Kernel 2: fused double-cdist + mix. 128 threads = two 64-thread s-groups.
// 8x8 micro-tile with ROW-PAIRED fp32x2 accumulators:
//   A stored transposed AT[k][row]; LDS.64 gives rows (2ty+16i, 2ty+16i+1)
//   at one k; b broadcast pack2(b,b). acc[i][j].x/.y = full dots for the
//   row pair -> 32 u64 accumulators (64 regs) instead of 128.
// ---------------------------------------------------------------------------
__global__ void __launch_bounds__(128) dist_kernel(
    const float* __restrict__ wxp,
    float* __restrict__ out)
{
    __shared__ __align__(16) float sAT[2][NPOS * ATPAD];   // [k][row]
    __shared__ __align__(16) float sB[2][64 * KPAD];       // [col][k]
    __shared__ float nA[2][64];
    __shared__ float nB[2][64];
    __shared__ float xch[64 * 65];

    int bz = blockIdx.y;
    int u = blockIdx.x;
    int ti = 0;
    #pragma unroll 1
    while (u >= (9 - ti)) { u -= (9 - ti); ti++; }
    int tj = ti + u;
    int p0 = ti * 64;
    int q0 = tj * 64;

    int t  = threadIdx.x;     // 0..127
    int sg = t >> 6;          // s-path group
    int lt = t & 63;
    int tx = lt & 7;
    int ty = lt >> 3;

    // Load: A transposed-scatter, B row-major float4.
    #pragma unroll
    for (int s = 0; s < 2; s++) {
        const float* V = s ? g_Vy : g_Vx;
        const float4* ga = (const float4*)(V + ((size_t)bz * SEQ + p0) * NPOS);
        const float4* gb = (const float4*)(V + ((size_t)bz * SEQ + q0) * NPOS);
        for (int idx = t; idx < 64 * NPOS / 4; idx += 128) {   // 384 float4
            int r = idx / 6, c = (idx - r * 6) * 4;
            float4 va = ga[idx];
            sAT[s][(c + 0) * ATPAD + r] = va.x;
            sAT[s][(c + 1) * ATPAD + r] = va.y;
            sAT[s][(c + 2) * ATPAD + r] = va.z;
            sAT[s][(c + 3) * ATPAD + r] = va.w;
            *(float4*)&sB[s][r * KPAD + c] = gb[idx];
        }
    }
    __syncthreads();

    // Norms: 256 tasks on 128 threads. nA from AT columns, nB from B rows.
    for (int o = t; o < 256; o += 128) {
        int s  = (o >> 7) & 1;
        int ab = (o >> 6) & 1;
        int r  = o & 63;
        float acc = 0.0f;
        if (ab) {
            const float* src = &sB[s][r * KPAD];
            #pragma unroll
            for (int k = 0; k < NPOS; k++)
                acc = fmaf(src[k], src[k], acc);
            nB[s][r] = acc;
        } else {
            const float* src = &sAT[s][r];
            #pragma unroll
            for (int k = 0; k < NPOS; k++) {
                float v = src[k * ATPAD];
                acc = fmaf(v, v, acc);
            }
            nA[s][r] = acc;
        }
    }
    __syncthreads();

    float wxv = *wxp;

    // Gram mainloop for this group's path.
    const float* ATs = sAT[sg];
    const float* Bs  = sB[sg];
    unsigned long long acc[4][8];
    #pragma unroll
    for (int i = 0; i < 4; i++)
        #pragma unroll
        for (int j = 0; j < 8; j++) acc[i][j] = 0ull;

    #pragma unroll
    for (int k = 0; k < NPOS; k++) {
        unsigned long long a2[4];
        unsigned long long b2[8];
        #pragma unroll
        for (int i = 0; i < 4; i++)
            a2[i] = *(const unsigned long long*)(ATs + k * ATPAD + 2 * ty + 16 * i);
        #pragma unroll
        for (int j = 0; j < 8; j++) {
            float b = Bs[(tx + 8 * j) * KPAD + k];
            b2[j] = pack2(b, b);
        }
        #pragma unroll
        for (int i = 0; i < 4; i++)
            #pragma unroll
            for (int j = 0; j < 8; j++)
                acc[i][j] = fma2(a2[i], b2[j], acc[i][j]);
    }

    // Epilogue: acc[i][j].x = G(row 2ty+16i,   col tx+8j)
    //           acc[i][j].y = G(row 2ty+16i+1, col tx+8j)
    if (sg == 1) {
        float scale = 1.0f - wxv;
        #pragma unroll
        for (int i = 0; i < 4; i++) {
            int r = 2 * ty + 16 * i;
            float na0 = nA[1][r], na1 = nA[1][r + 1];
            #pragma unroll
            for (int j = 0; j < 8; j++) {
                int c = tx + 8 * j;
                float nb = nB[1][c];
                float2 g = *(float2*)&acc[i][j];
                float d20 = fmaxf(fmaf(-2.0f, g.x, na0 + nb), 0.0f);
                float d21 = fmaxf(fmaf(-2.0f, g.y, na1 + nb), 0.0f);
                xch[r * 65 + c]       = scale * fsqrt_approx(d20);
                xch[(r + 1) * 65 + c] = scale * fsqrt_approx(d21);
            }
        }
    }
    __syncthreads();

    if (sg == 0) {
        float scale = wxv;
        #pragma unroll
        for (int i = 0; i < 4; i++) {
            int r = 2 * ty + 16 * i;
            float na0 = nA[0][r], na1 = nA[0][r + 1];
            #pragma unroll
            for (int j = 0; j < 8; j++) {
                int c = tx + 8 * j;
                float nb = nB[0][c];
                float2 g = *(float2*)&acc[i][j];
                float d20 = fmaxf(fmaf(-2.0f, g.x, na0 + nb), 0.0f);
                float d21 = fmaxf(fmaf(-2.0f, g.y, na1 + nb), 0.0f);
                float f0 = fmaf(scale, fsqrt_approx(d20), xch[r * 65 + c]);
                float f1 = fmaf(scale, fsqrt_approx(d21), xch[(r + 1) * 65 + c]);
                if (p0 + r == q0 + c)     f0 = 0.0f;
                if (p0 + r + 1 == q0 + c) f1 = 0.0f;
                xch[r * 65 + c]       = f0;
                xch[(r + 1) * 65 + c] = f1;
            }
        }
    }
    __syncthreads();

    // Primary tile: coalesced float4 writes
    for (int idx = t; idx < 1024; idx += 128) {
        int r = idx >> 4, c = (idx & 15) * 4;
        const float* xr = &xch[r * 65 + c];
        float4 v = make_float4(xr[0], xr[1], xr[2], xr[3]);
        *(float4*)(out + ((size_t)bz * SEQ + (p0 + r)) * SEQ + q0 + c) = v;
    }

    // Mirror tile for off-diagonal pairs
    if (ti != tj) {
        for (int idx = t; idx < 1024; idx += 128) {
            int r = idx >> 4, c = (idx & 15) * 4;
            float4 v = make_float4(xch[(c + 0) * 65 + r],
                                   xch[(c + 1) * 65 + r],
                                   xch[(c + 2) * 65 + r],
                                   xch[(c + 3) * 65 + r]);
            *(float4*)(out + ((size_t)bz * SEQ + (q0 + r)) * SEQ + p0 + c) = v;
        }
    }
}

// ---------------------------------------------------------------------------
extern "C" void kernel_launch(void* const* d_in, const int* in_sizes, int n_in,
                              void* d_out, int out_size) {
    const float* query = (const float*)d_in[0];
    const float* attn  = (const float*)d_in[1];
    const float* pex   = (const float*)d_in[2];
    const float* pey   = (const float*)d_in[3];
    const float* wx    = (const float*)d_in[4];
    float* out = (float*)d_out;

    cope_kernel<<<2304, 512>>>(query, attn, pex, pey);

    dim3 dgrid(45, BATCH);
    dist_kernel<<<dgrid, 128>>>(wx, out);
}